// round 9
// baseline (speedup 1.0000x reference)
#include <cuda_runtime.h>
#include <math.h>

#define NSC   48
#define RMAX  11
#define NCTA  (3*NSC)
#define T     384

#define GW0_F4 (76*64)     // 4864 f4 per scale
#define GW0_A  2560        // chunk A: k 0..39 (40 rows)
#define GW0_B  2304        // chunk B: k 40..75 (36 rows)
#define GW1_F4 (128*64)
#define PAN_F4 2560        // 40KB panel
#define DYN_SMEM ((GW1_F4 + PAN_F4) * 16)   // 172,032 bytes

__device__ float4 g_gw0p[3*GW0_F4];
__device__ float4 g_gw1p[3*GW1_F4];
__device__ __align__(16) float g_Wa[6*64*64];
__device__ float g_ba[6*64];
__device__ float g_outs[3ull*512*512*64];

__device__ __forceinline__ float sigmf(float v){
    return __fdividef(1.0f, 1.0f + __expf(-v));
}
__device__ __forceinline__ float tanhfast(float v){
    return 1.0f - __fdividef(2.0f, __expf(2.0f*v) + 1.0f);
}

template<int N>
__device__ __forceinline__ void cpyp(float4* d, const float4* __restrict__ s, int tid){
    #pragma unroll
    for (int i = 0; i < (N + T - 1)/T; i++){
        int j = tid + i*T;
        if (j < N) d[j] = s[j];
    }
}

// 8-FMA gate step: float4 weights (4 gates), 2 rows
#define GK(wv, za, zb) do{ float4 _w = (wv); \
    accA.x = fmaf((za),_w.x,accA.x); accA.y = fmaf((za),_w.y,accA.y); \
    accA.z = fmaf((za),_w.z,accA.z); accA.w = fmaf((za),_w.w,accA.w); \
    accB.x = fmaf((zb),_w.x,accB.x); accB.y = fmaf((zb),_w.y,accB.y); \
    accB.z = fmaf((zb),_w.z,accB.z); accB.w = fmaf((zb),_w.w,accB.w); }while(0)

#define GBLK(wp, koff, actA_, actB_, aoff) do{ \
    float4 zA = *(const float4*)((actA_) + (aoff)); \
    float4 zB = *(const float4*)((actB_) + (aoff)); \
    GK((wp)[((koff)  )*64 + sc], zA.x, zB.x); \
    GK((wp)[((koff)+1)*64 + sc], zA.y, zB.y); \
    GK((wp)[((koff)+2)*64 + sc], zA.z, zB.z); \
    GK((wp)[((koff)+3)*64 + sc], zA.w, zB.w); }while(0)

// 2-row stage step: scalar weight
#define SK(wv, za, zb) do{ float _w=(wv); a0 = fmaf((za),_w,a0); a1 = fmaf((zb),_w,a1); }while(0)
#define SBLK(wp, stride, koff, zAp, zBp, aoff) do{ \
    float4 zA = *(const float4*)((zAp)+(aoff)); \
    float4 zB = *(const float4*)((zBp)+(aoff)); \
    SK((wp)[((koff)  )*(stride)+sc], zA.x, zB.x); \
    SK((wp)[((koff)+1)*(stride)+sc], zA.y, zB.y); \
    SK((wp)[((koff)+2)*(stride)+sc], zA.z, zB.z); \
    SK((wp)[((koff)+3)*(stride)+sc], zA.w, zB.w); }while(0)

__global__ void pack_gw_kernel(const float* __restrict__ gw0, const float* __restrict__ gw1){
    int i = blockIdx.x*blockDim.x + threadIdx.x;
    float* p0 = (float*)g_gw0p;
    float* p1 = (float*)g_gw1p;
    if (i < 3*76*256){
        int s = i/(76*256), rem = i%(76*256), k = rem/256, j = rem%256;
        p0[(s*76 + k)*256 + ((j&63)<<2) + (j>>6)] = gw0[i];
    }
    if (i < 3*128*256){
        int s = i/(128*256), rem = i%(128*256), k = rem/256, j = rem%256;
        p1[(s*128 + k)*256 + ((j&63)<<2) + (j>>6)] = gw1[i];
    }
}

__global__ void compute_wa_kernel(const float* __restrict__ mi_w, const float* __restrict__ mi_b,
                                  const float* __restrict__ mo_w, const float* __restrict__ mo_b){
    int sl = blockIdx.x;
    const float* miw = mi_w + (size_t)sl*64*192;
    const float* mow = mo_w + (size_t)sl*64*64;
    for (int idx = threadIdx.x; idx < 64*64; idx += blockDim.x){
        int k = idx>>6, n = idx&63;
        float acc = 0.f;
        #pragma unroll 8
        for (int j=0;j<64;j++) acc += miw[k*192 + 128 + j] * mow[j*64 + n];
        g_Wa[sl*4096 + k*64 + n] = acc;
    }
    if (threadIdx.x < 64){
        int n = threadIdx.x;
        float acc = mo_b[sl*64 + n];
        #pragma unroll 8
        for (int j=0;j<64;j++) acc += mi_b[sl*192 + 128 + j] * mow[j*64 + n];
        g_ba[sl*64 + n] = acc;
    }
}

__global__ void __launch_bounds__(T, 1) xlstm_kernel(
    const float* __restrict__ x,
    const float* __restrict__ gb0, const float* __restrict__ gb1,
    const float* __restrict__ w1,  const float* __restrict__ b1,
    const float* __restrict__ w2,  const float* __restrict__ b2,
    const float* __restrict__ lag, const float* __restrict__ lab,
    const float* __restrict__ logw,const float* __restrict__ lob,
    const float* __restrict__ rw0, const float* __restrict__ rb0,
    const float* __restrict__ rw1, const float* __restrict__ rb1)
{
    const int cta = blockIdx.x;
    const int s   = cta / NSC;
    const int ci  = cta % NSC;
    const int base  = (ci < 32) ? ci*11 : 352 + (ci-32)*10;
    const int nrows = (ci < 32) ? 11 : 10;
    const int tid  = threadIdx.x;
    const int m    = tid & 63;
    const int rg   = tid >> 6;
    const int lane = tid & 31;
    const int wrp  = tid >> 5;

    // row-blocked mapping: 3 row-groups x 4 rows, 4 col-groups
    const int rowg = wrp >> 2;          // 0..2
    const int colq = wrp & 3;           // 0..3
    const int cl   = lane & 15;
    const int rh   = lane >> 4;
    const int sc   = colq*16 + cl;      // 0..63 (64-wide stages & gates)
    const int fc   = colq*32 + lane;    // 0..127 (ff1)
    const int dr0  = rowg + 6*rh;       // rows {rowg, rowg+6}
    const int dr1  = dr0 + 3;           // rows {rowg+3, rowg+9}
    const int cr0  = (dr0 < nrows) ? dr0 : 0;
    const int cr1  = (dr1 < nrows) ? dr1 : 0;
    const bool v0  = (dr0 < nrows), v1 = (dr1 < nrows);

    extern __shared__ float4 dynsm[];
    float4* s_gw1 = dynsm;               // resident 128KB
    float4* pan4  = dynsm + GW1_F4;      // 40KB panel
    float*  panf  = (float*)pan4;

    __shared__ __align__(16) float sh_h0[RMAX][64], sh_h1[RMAX][64];
    __shared__ __align__(16) float sh_x[RMAX][12];
    __shared__ __align__(16) float sh_hy[RMAX][64];
    __shared__ __align__(16) float sh_a[RMAX][64];
    __shared__ __align__(16) float sh_t1[RMAX][128];
    __shared__ __align__(16) float sh_inp[RMAX][64];
    __shared__ float sh_stat[RMAX][2];
    __shared__ __align__(16) float sb_ba[2][64];
    __shared__ __align__(16) float sb_b1[2][128];
    __shared__ __align__(16) float sb_b2[2][64];
    __shared__ __align__(16) float sb_rb1[64];
    __shared__ __align__(16) float s_rw0[12*64];
    __shared__ __align__(16) float s_rw1[64*64];

    {
        const float4* g1 = g_gw1p + (size_t)s*GW1_F4;
        for (int i=tid;i<GW1_F4;i+=T) s_gw1[i] = g1[i];
        const float* rw1s = rw1 + (size_t)s*4096;
        for (int i=tid;i<4096;i+=T) s_rw1[i] = rw1s[i];
        const float* rw0s = rw0 + (size_t)s*768;
        for (int i=tid;i<768;i+=T) s_rw0[i] = rw0s[i];
        for (int i = tid; i < RMAX*64; i += T){ ((float*)sh_h0)[i] = 0.f; ((float*)sh_h1)[i] = 0.f; }
        if (tid < 128){
            sb_b1[0][tid] = b1[(s*2+0)*128 + tid];
            sb_b1[1][tid] = b1[(s*2+1)*128 + tid];
        }
        if (tid < 64){
            sb_ba[0][tid] = g_ba[(s*2+0)*64 + tid];
            sb_ba[1][tid] = g_ba[(s*2+1)*64 + tid];
            sb_b2[0][tid] = b2[(s*2+0)*64 + tid];
            sb_b2[1][tid] = b2[(s*2+1)*64 + tid];
            sb_rb1[tid]   = rb1[s*64 + tid];
        }
    }
    // gate biases per thread (col = sc), shared by both rows
    const float4 r_gb0 = make_float4(gb0[s*256+sc], gb0[s*256+64+sc], gb0[s*256+128+sc], gb0[s*256+192+sc]);
    const float4 r_gb1 = make_float4(gb1[s*256+sc], gb1[s*256+64+sc], gb1[s*256+128+sc], gb1[s*256+192+sc]);
    // LN params (old mapping, col=m)
    const float r_lag0 = lag[(s*2+0)*64+m],  r_lag1 = lag[(s*2+1)*64+m];
    const float r_lab0 = lab[(s*2+0)*64+m],  r_lab1 = lab[(s*2+1)*64+m];
    const float r_log0 = logw[(s*2+0)*64+m], r_log1 = logw[(s*2+1)*64+m];
    const float r_lob0 = lob[(s*2+0)*64+m],  r_lob1 = lob[(s*2+1)*64+m];
    const float r_rb0  = rb0[s*64+m];
    __syncthreads();

    // old-mapping row lists (LN chain + inp stage)
    int myr[2]; int nmy = 0;
    #pragma unroll
    for (int q=0;q<2;q++){ int r = rg + 6*q; myr[q] = (r < nrows) ? r : (nrows-1); if (r < nrows) nmy = q+1; }
    // ff1 rows (4 per warp)
    int frr[4]; bool fv[4];
    #pragma unroll
    for (int j=0;j<4;j++){ int r = rowg + 3*j; fv[j] = (r < nrows); frr[j] = fv[j] ? r : 0; }

    // cell states: (dr0, sc) and (dr1, sc)
    float c0A = 0.f, c0B = 0.f, c1A = 0.f, c1B = 0.f;

    const float4* gw0g  = g_gw0p + (size_t)s*GW0_F4;
    const float4* Wa0_4 = (const float4*)g_Wa + (size_t)(s*2+0)*1024;
    const float4* Wa1_4 = (const float4*)g_Wa + (size_t)(s*2+1)*1024;
    const float4* w10_4 = (const float4*)(w1 + (size_t)(s*2+0)*8192);
    const float4* w11_4 = (const float4*)(w1 + (size_t)(s*2+1)*8192);
    const float4* w20_4 = (const float4*)(w2 + (size_t)(s*2+0)*8192);
    const float4* w21_4 = (const float4*)(w2 + (size_t)(s*2+1)*8192);

    const int Li  = (s==0) ? 170 : (s==1 ? 512 : 256);
    const int st0 = (s==0) ? 342 : (s==1 ? 0   : 256);
    const float scf = (float)Li / 512.0f;

    float* outbase = g_outs + ((size_t)s*512 + base)*512*64;

    auto ln_pass = [&](){
        if (wrp < nrows){
            int r = wrp;
            float va = sh_hy[r][lane], vb = sh_hy[r][lane+32];
            float sm = va + vb, sq = va*va + vb*vb;
            #pragma unroll
            for (int o=16;o;o>>=1){
                sm += __shfl_xor_sync(0xffffffffu, sm, o);
                sq += __shfl_xor_sync(0xffffffffu, sq, o);
            }
            if (lane == 0){
                float mean = sm * 0.015625f;
                float var  = sq * 0.015625f - mean*mean;
                sh_stat[r][0] = mean;
                sh_stat[r][1] = rsqrtf(var + 1e-5f);
            }
        }
    };

    auto ln_chain = [&](float (*hstate)[64], float* hn_out,
                        float lag_r, float lab_r, float log_r, float lob_r){
        ln_pass();
        __syncthreads();
        #pragma unroll
        for (int q=0;q<2;q++){
            int r = myr[q];
            float v  = sh_hy[r][m];
            float ln = (v - sh_stat[r][0]) * sh_stat[r][1] * lag_r + lab_r;
            float yv = ln + hstate[r][m];
            if (q < nmy) sh_hy[r][m] = yv;
        }
        __syncthreads();
        ln_pass();
        __syncthreads();
        #pragma unroll
        for (int q=0;q<2;q++){
            int r = myr[q];
            float yv = sh_hy[r][m];
            float hn = (yv - sh_stat[r][0]) * sh_stat[r][1] * log_r + lob_r;
            hn_out[q] = hn;
            if (q < nmy) hstate[r][m] = hn;
        }
    };

    // attn: a[r][sc] = ba + sum_k hy[r][k]*Wa[k][sc]   (k=64, panel stride 64)
    auto attn_stage = [&](int l){
        float a0 = sb_ba[l][sc], a1 = a0;
        #pragma unroll
        for (int b=0;b<16;b++) SBLK(panf, 64, b*4, sh_hy[cr0], sh_hy[cr1], b*4);
        if (v0) sh_a[dr0][sc] = a0;
        if (v1) sh_a[dr1][sc] = a1;
    };
    // ff1: t1[r][fc] = gelu(b1 + sum_k a[r][k]*w1[k][fc])  (k=64, stride 128, 4 rows)
    auto ff1_stage = [&](int l){
        float t0 = sb_b1[l][fc], t1v = t0, t2 = t0, t3 = t0;
        #pragma unroll
        for (int b=0;b<16;b++){
            float4 z0 = *(const float4*)&sh_a[frr[0]][b*4];
            float4 z1 = *(const float4*)&sh_a[frr[1]][b*4];
            float4 z2 = *(const float4*)&sh_a[frr[2]][b*4];
            float4 z3 = *(const float4*)&sh_a[frr[3]][b*4];
            float w0 = panf[(b*4  )*128 + fc];
            float w1_ = panf[(b*4+1)*128 + fc];
            float w2_ = panf[(b*4+2)*128 + fc];
            float w3_ = panf[(b*4+3)*128 + fc];
            t0 = fmaf(z0.x,w0,t0); t0 = fmaf(z0.y,w1_,t0); t0 = fmaf(z0.z,w2_,t0); t0 = fmaf(z0.w,w3_,t0);
            t1v= fmaf(z1.x,w0,t1v);t1v= fmaf(z1.y,w1_,t1v);t1v= fmaf(z1.z,w2_,t1v);t1v= fmaf(z1.w,w3_,t1v);
            t2 = fmaf(z2.x,w0,t2); t2 = fmaf(z2.y,w1_,t2); t2 = fmaf(z2.z,w2_,t2); t2 = fmaf(z2.w,w3_,t2);
            t3 = fmaf(z3.x,w0,t3); t3 = fmaf(z3.y,w1_,t3); t3 = fmaf(z3.z,w2_,t3); t3 = fmaf(z3.w,w3_,t3);
        }
        const float c = 0.7071067811865475f;
        float g0 = 0.5f*t0 *(1.0f + erff(t0 *c));
        float g1 = 0.5f*t1v*(1.0f + erff(t1v*c));
        float g2 = 0.5f*t2 *(1.0f + erff(t2 *c));
        float g3 = 0.5f*t3 *(1.0f + erff(t3 *c));
        if (fv[0]) sh_t1[frr[0]][fc] = g0;
        if (fv[1]) sh_t1[frr[1]][fc] = g1;
        if (fv[2]) sh_t1[frr[2]][fc] = g2;
        if (fv[3]) sh_t1[frr[3]][fc] = g3;
    };
    // ff2: y[r][sc] = b2 + sum_k t1[r][k]*w2[k][sc]   (k=128, stride 64)
    auto ff2_stage = [&](int l){
        float a0 = sb_b2[l][sc], a1 = a0;
        #pragma unroll
        for (int b=0;b<32;b++) SBLK(panf, 64, b*4, sh_t1[cr0], sh_t1[cr1], b*4);
        if (v0) sh_hy[dr0][sc] = a0;
        if (v1) sh_hy[dr1][sc] = a1;
    };

    for (int t=0; t<512; t++){
        // stage gw0 chunk A + x upsample
        cpyp<GW0_A>(pan4, gw0g, tid);
        {
            float srcf = fmaxf((t + 0.5f) * scf - 0.5f, 0.0f);
            int i0 = (int)srcf;
            if (i0 > Li-1) i0 = Li-1;
            int i1 = min(i0+1, Li-1);
            float wu = srcf - (float)i0;
            if (tid < nrows*12){
                int r = tid/12, k = tid%12;
                const float* xb = x + ((size_t)(base+r)*512 + st0)*12;
                float va = xb[i0*12 + k], vb = xb[i1*12 + k];
                sh_x[r][k] = va*(1.0f - wu) + vb*wu;
            }
        }
        __syncthreads();                              // S1: gw0A + sh_x ready

        // ---- gates layer 0 ----
        float4 accA = r_gb0, accB = r_gb0;
        #pragma unroll
        for (int b=0;b<3;b++) GBLK(pan4, b*4,      sh_x[cr0],  sh_x[cr1],  b*4);       // k 0..11
        #pragma unroll
        for (int b=0;b<7;b++) GBLK(pan4, 12+b*4,   sh_h0[cr0], sh_h0[cr1], b*4);       // k 12..39
        __syncthreads();                              // S2: panel free
        cpyp<GW0_B>(pan4, gw0g + GW0_A, tid);
        __syncthreads();                              // S3: gw0B ready
        #pragma unroll
        for (int b=0;b<9;b++) GBLK(pan4, b*4,      sh_h0[cr0], sh_h0[cr1], 28+b*4);    // k 40..75
        {
            float cnA = sigmf(accA.x)*c0A + sigmf(accA.y)*tanhfast(accA.z);
            float htA = sigmf(accA.w)*tanhfast(cnA);
            float cnB = sigmf(accB.x)*c0B + sigmf(accB.y)*tanhfast(accB.z);
            float htB = sigmf(accB.w)*tanhfast(cnB);
            if (v0){ c0A = cnA; sh_hy[dr0][sc] = htA; }
            if (v1){ c0B = cnB; sh_hy[dr1][sc] = htB; }
        }
        __syncthreads();                              // S4: hy ready, panel free
        cpyp<1024>(pan4, Wa0_4, tid);
        __syncthreads();                              // S5
        attn_stage(0);
        __syncthreads();                              // S6
        cpyp<2048>(pan4, w10_4, tid);
        __syncthreads();                              // S7
        ff1_stage(0);
        __syncthreads();                              // S8
        cpyp<2048>(pan4, w20_4, tid);
        __syncthreads();                              // S9
        ff2_stage(0);
        __syncthreads();                              // S10
        float h0n[2];
        ln_chain(sh_h0, h0n, r_lag0, r_lab0, r_log0, r_lob0);
        #pragma unroll
        for (int q=0;q<2;q++){
            int r = myr[q];
            float acc = h0n[q] + r_rb0;
            #pragma unroll
            for (int k=0;k<12;k++) acc += sh_x[r][k] * s_rw0[k*64 + m];
            if (q < nmy) sh_inp[r][m] = acc;
        }
        __syncthreads();                              // S14: sh_inp + sh_h0 ready
        cpyp<1024>(pan4, Wa1_4, tid);

        // ---- gates layer 1 (resident) ----
        accA = r_gb1; accB = r_gb1;
        #pragma unroll
        for (int b=0;b<16;b++) GBLK(s_gw1, b*4,    sh_inp[cr0], sh_inp[cr1], b*4);     // k 0..63
        #pragma unroll
        for (int b=0;b<16;b++) GBLK(s_gw1, 64+b*4, sh_h1[cr0],  sh_h1[cr1],  b*4);     // k 64..127
        {
            float cnA = sigmf(accA.x)*c1A + sigmf(accA.y)*tanhfast(accA.z);
            float htA = sigmf(accA.w)*tanhfast(cnA);
            float cnB = sigmf(accB.x)*c1B + sigmf(accB.y)*tanhfast(accB.z);
            float htB = sigmf(accB.w)*tanhfast(cnB);
            if (v0){ c1A = cnA; sh_hy[dr0][sc] = htA; }
            if (v1){ c1B = cnB; sh_hy[dr1][sc] = htB; }
        }
        __syncthreads();                              // S15: Wa1 + hy ready
        attn_stage(1);
        __syncthreads();                              // S16
        cpyp<2048>(pan4, w11_4, tid);
        __syncthreads();                              // S17
        ff1_stage(1);
        __syncthreads();                              // S18
        cpyp<2048>(pan4, w21_4, tid);
        __syncthreads();                              // S19
        ff2_stage(1);
        __syncthreads();                              // S20
        float h1n[2];
        ln_chain(sh_h1, h1n, r_lag1, r_lab1, r_log1, r_lob1);
        __syncthreads();                              // S24: sh_h1 ready

        // ---- out = h1 + inp@rw1 + rb1 (row-blocked mapping) ----
        {
            float a0 = sb_rb1[sc] + sh_h1[cr0][sc];
            float a1 = sb_rb1[sc] + sh_h1[cr1][sc];
            #pragma unroll
            for (int b=0;b<16;b++) SBLK(s_rw1, 64, b*4, sh_inp[cr0], sh_inp[cr1], b*4);
            if (v0) outbase[((size_t)dr0*512 + t)*64 + sc] = a0;
            if (v1) outbase[((size_t)dr1*512 + t)*64 + sc] = a1;
        }
        __syncthreads();                              // S25
    }
}

__global__ void merge_kernel(const float* __restrict__ attn_w, float* __restrict__ out){
    int warp = (blockIdx.x*blockDim.x + threadIdx.x) >> 5;
    int lane = threadIdx.x & 31;
    if (warp >= 512*512) return;
    const size_t SS = 512ull*512*64;
    const float* p = g_outs + (size_t)warp*64;
    float aw0 = attn_w[lane], aw1 = attn_w[lane+32];
    float v0[3], v1[3], sc[3];
    #pragma unroll
    for (int si=0; si<3; si++){
        v0[si] = p[si*SS + lane];
        v1[si] = p[si*SS + lane + 32];
        float d = v0[si]*aw0 + v1[si]*aw1;
        #pragma unroll
        for (int o=16;o;o>>=1) d += __shfl_xor_sync(0xffffffffu, d, o);
        sc[si] = d;
    }
    float mx = fmaxf(sc[0], fmaxf(sc[1], sc[2]));
    float e0 = __expf(sc[0]-mx), e1 = __expf(sc[1]-mx), e2 = __expf(sc[2]-mx);
    float inv = __fdividef(1.0f, e0+e1+e2);
    float wt0 = e0*inv, wt1 = e1*inv, wt2 = e2*inv;
    out[(size_t)warp*64 + lane]      = v0[0]*wt0 + v0[1]*wt1 + v0[2]*wt2;
    out[(size_t)warp*64 + lane + 32] = v1[0]*wt0 + v1[1]*wt1 + v1[2]*wt2;
}

extern "C" void kernel_launch(void* const* d_in, const int* in_sizes, int n_in,
                              void* d_out, int out_size){
    const float* x     = (const float*)d_in[0];
    const float* gw0   = (const float*)d_in[1];
    const float* gb0   = (const float*)d_in[2];
    const float* gw1   = (const float*)d_in[3];
    const float* gb1   = (const float*)d_in[4];
    const float* mi_w  = (const float*)d_in[5];
    const float* mi_b  = (const float*)d_in[6];
    const float* mo_w  = (const float*)d_in[7];
    const float* mo_b  = (const float*)d_in[8];
    const float* w1    = (const float*)d_in[9];
    const float* b1    = (const float*)d_in[10];
    const float* w2    = (const float*)d_in[11];
    const float* b2    = (const float*)d_in[12];
    const float* lag   = (const float*)d_in[13];
    const float* lab   = (const float*)d_in[14];
    const float* logw  = (const float*)d_in[15];
    const float* lob   = (const float*)d_in[16];
    const float* rw0   = (const float*)d_in[17];
    const float* rb0   = (const float*)d_in[18];
    const float* rw1   = (const float*)d_in[19];
    const float* rb1   = (const float*)d_in[20];
    const float* attnw = (const float*)d_in[21];
    float* out = (float*)d_out;

    static int smem_set = 0;
    if (!smem_set){
        cudaFuncSetAttribute(xlstm_kernel, cudaFuncAttributeMaxDynamicSharedMemorySize, DYN_SMEM);
        smem_set = 1;
    }

    pack_gw_kernel<<<(3*128*256 + 255)/256, 256>>>(gw0, gw1);
    compute_wa_kernel<<<6, 256>>>(mi_w, mi_b, mo_w, mo_b);
    xlstm_kernel<<<NCTA, T, DYN_SMEM>>>(x, gb0, gb1, w1, b1, w2, b2,
                                        lag, lab, logw, lob, rw0, rb0, rw1, rb1);
    merge_kernel<<<(512*512*32 + 255)/256, 256>>>(attnw, out);
}